// round 14
// baseline (speedup 1.0000x reference)
#include <cuda_runtime.h>
#include <cuda_fp16.h>
#include <stdint.h>

#define MAX_NODES 100000
#define D 128
#define CAP 96            // bucket capacity per node (P(overflow) ~ e^-100)

typedef unsigned long long ull;

// ---- device scratch ----
__device__ __align__(256) int   g_cnt[MAX_NODES];
__device__ __align__(256) ull   g_pairs[(size_t)MAX_NODES * CAP];  // (wt<<32 | src*512)
__device__ __align__(256) float g_agg[(size_t)MAX_NODES * D];

// ---------------------------------------------------------------------------
// Bucket fill: 4 edges/thread -> 4 independent atomic->scatter chains (MLP=4).
__global__ void fill_kernel(const int* __restrict__ ei,
                            const float* __restrict__ ew, int E, int N) {
    int t = blockIdx.x * blockDim.x + threadIdx.x;
    int base = t * 4;
    if (base + 4 <= E) {
        int4 s = *(const int4*)(ei + base);
        int4 d = *(const int4*)(ei + E + base);
        float4 w = *(const float4*)(ew + base);
        if ((unsigned)d.x < (unsigned)N) {
            int pos = atomicAdd(&g_cnt[d.x], 1);
            if (pos < CAP) g_pairs[(size_t)d.x * CAP + pos] =
                ((ull)__float_as_uint(w.x) << 32) | ((unsigned)s.x << 9);
        }
        if ((unsigned)d.y < (unsigned)N) {
            int pos = atomicAdd(&g_cnt[d.y], 1);
            if (pos < CAP) g_pairs[(size_t)d.y * CAP + pos] =
                ((ull)__float_as_uint(w.y) << 32) | ((unsigned)s.y << 9);
        }
        if ((unsigned)d.z < (unsigned)N) {
            int pos = atomicAdd(&g_cnt[d.z], 1);
            if (pos < CAP) g_pairs[(size_t)d.z * CAP + pos] =
                ((ull)__float_as_uint(w.z) << 32) | ((unsigned)s.z << 9);
        }
        if ((unsigned)d.w < (unsigned)N) {
            int pos = atomicAdd(&g_cnt[d.w], 1);
            if (pos < CAP) g_pairs[(size_t)d.w * CAP + pos] =
                ((ull)__float_as_uint(w.w) << 32) | ((unsigned)s.w << 9);
        }
    } else {
        for (int e = base; e < E; e++) {
            int src = ei[e];
            int dst = ei[E + e];
            if ((unsigned)dst < (unsigned)N && (unsigned)src < (unsigned)N) {
                int pos = atomicAdd(&g_cnt[dst], 1);
                if (pos < CAP) g_pairs[(size_t)dst * CAP + pos] =
                    ((ull)__float_as_uint(ew[e]) << 32) | ((unsigned)src << 9);
            }
        }
    }
}

// One warp per 4 nodes; 2-deep gather, pre-scaled byte offsets, <=32 regs.
__global__ __launch_bounds__(256, 8)
void aggregate_kernel(const float* __restrict__ x, int n) {
    int warp = (blockIdx.x * blockDim.x + threadIdx.x) >> 5;
    int lane = threadIdx.x & 31;
    const char* xb = (const char*)x + lane * 16;   // lane's 16B slice base
    int node = warp * 4;
    #pragma unroll 1
    for (int j = 0; j < 4; j++, node++) {
        if (node >= n) return;
        int cnt = g_cnt[node];
        int end = (cnt < CAP) ? cnt : CAP;
        const ull* pp = g_pairs + (size_t)node * CAP;
        float4 a0 = make_float4(0.f, 0.f, 0.f, 0.f);
        float4 a1 = make_float4(0.f, 0.f, 0.f, 0.f);
        int i = 0;
        for (; i + 2 <= end; i += 2) {
            ull p0 = pp[i];
            ull p1 = pp[i + 1];
            float4 v0 = *(const float4*)(xb + (unsigned)p0);
            float4 v1 = *(const float4*)(xb + (unsigned)p1);
            float w0 = __uint_as_float((unsigned)(p0 >> 32));
            float w1 = __uint_as_float((unsigned)(p1 >> 32));
            a0.x += w0 * v0.x; a0.y += w0 * v0.y; a0.z += w0 * v0.z; a0.w += w0 * v0.w;
            a1.x += w1 * v1.x; a1.y += w1 * v1.y; a1.z += w1 * v1.z; a1.w += w1 * v1.w;
        }
        if (i < end) {
            ull p = pp[i];
            float4 v = *(const float4*)(xb + (unsigned)p);
            float w = __uint_as_float((unsigned)(p >> 32));
            a0.x += w * v.x; a0.y += w * v.y; a0.z += w * v.z; a0.w += w * v.w;
        }
        float4 r = make_float4(a0.x + a1.x, a0.y + a1.y, a0.z + a1.z, a0.w + a1.w);
        *(float4*)(g_agg + (size_t)node * D + lane * 4) = r;
    }
}

// ============================================================================
// HMMA GEMM (identical to round-10): mma.sync m16n8k16 f16->f32.
// ============================================================================

#define SH_STRIDE 136

__device__ __forceinline__ uint32_t smem_u32(const void* p) {
    return (uint32_t)__cvta_generic_to_shared(p);
}

__device__ __forceinline__ void ldsm_x4(uint32_t& r0, uint32_t& r1,
                                        uint32_t& r2, uint32_t& r3, uint32_t a) {
    asm volatile("ldmatrix.sync.aligned.m8n8.x4.shared.b16 {%0,%1,%2,%3}, [%4];"
                 : "=r"(r0), "=r"(r1), "=r"(r2), "=r"(r3) : "r"(a));
}

__device__ __forceinline__ void hmma(float& c0, float& c1, float& c2, float& c3,
                                     uint32_t a0, uint32_t a1, uint32_t a2, uint32_t a3,
                                     uint32_t b0, uint32_t b1) {
    asm volatile("mma.sync.aligned.m16n8k16.row.col.f32.f16.f16.f32 "
                 "{%0,%1,%2,%3}, {%4,%5,%6,%7}, {%8,%9}, {%0,%1,%2,%3};"
                 : "+f"(c0), "+f"(c1), "+f"(c2), "+f"(c3)
                 : "r"(a0), "r"(a1), "r"(a2), "r"(a3), "r"(b0), "r"(b1));
}

#define GEMM_SMEM (2 * 128 * SH_STRIDE * 2)

__global__ __launch_bounds__(256) void gemm_hmma_kernel(const float* __restrict__ W,
                                                        const float* __restrict__ b,
                                                        float* __restrict__ out, int M) {
    extern __shared__ __align__(16) __half sh[];
    __half* sA = sh;
    __half* sW = sh + 128 * SH_STRIDE;
    const int tid  = threadIdx.x;
    const int wid  = tid >> 5;
    const int lane = tid & 31;
    const int mb   = blockIdx.x * 128;

    for (int idx = tid; idx < 128 * 32; idx += 256) {
        int r = idx >> 5, c4 = idx & 31;
        float4 v = ((const float4*)(W + r * 128))[c4];
        *(__half2*)&sW[r * SH_STRIDE + c4 * 4]     = __floats2half2_rn(v.x, v.y);
        *(__half2*)&sW[r * SH_STRIDE + c4 * 4 + 2] = __floats2half2_rn(v.z, v.w);
    }
    for (int idx = tid; idx < 128 * 32; idx += 256) {
        int r = idx >> 5, c4 = idx & 31;
        int row = mb + r;
        float4 v = (row < M) ? ((const float4*)(g_agg + (size_t)row * 128))[c4]
                             : make_float4(0.f, 0.f, 0.f, 0.f);
        *(__half2*)&sA[r * SH_STRIDE + c4 * 4]     = __floats2half2_rn(v.x, v.y);
        *(__half2*)&sA[r * SH_STRIDE + c4 * 4 + 2] = __floats2half2_rn(v.z, v.w);
    }
    __syncthreads();

    const int m0 = (wid & 3) * 32;
    const int n0 = (wid >> 2) * 64;

    float acc[2][8][4];
    #pragma unroll
    for (int i = 0; i < 2; i++)
        #pragma unroll
        for (int j = 0; j < 8; j++)
            #pragma unroll
            for (int q = 0; q < 4; q++) acc[i][j][q] = 0.f;

    const int a_row_off = lane & 15;
    const int a_col_off = (lane >> 4) * 8;
    const int b_row_off = (lane & 7) + ((lane >> 4) & 1) * 8;
    const int b_col_off = ((lane >> 3) & 1) * 8;

    #pragma unroll
    for (int kt = 0; kt < 8; kt++) {
        const int klo = kt * 16;
        uint32_t af[2][4];
        #pragma unroll
        for (int mf = 0; mf < 2; mf++) {
            uint32_t addr = smem_u32(&sA[(m0 + mf * 16 + a_row_off) * SH_STRIDE
                                         + klo + a_col_off]);
            ldsm_x4(af[mf][0], af[mf][1], af[mf][2], af[mf][3], addr);
        }
        uint32_t bf[8][2];
        #pragma unroll
        for (int g = 0; g < 4; g++) {
            uint32_t r0, r1, r2, r3;
            uint32_t addr = smem_u32(&sW[(n0 + g * 16 + b_row_off) * SH_STRIDE
                                         + klo + b_col_off]);
            ldsm_x4(r0, r1, r2, r3, addr);
            bf[g * 2][0] = r0; bf[g * 2][1] = r1;
            bf[g * 2 + 1][0] = r2; bf[g * 2 + 1][1] = r3;
        }
        #pragma unroll
        for (int mf = 0; mf < 2; mf++)
            #pragma unroll
            for (int nf = 0; nf < 8; nf++)
                hmma(acc[mf][nf][0], acc[mf][nf][1], acc[mf][nf][2], acc[mf][nf][3],
                     af[mf][0], af[mf][1], af[mf][2], af[mf][3],
                     bf[nf][0], bf[nf][1]);
    }

    const int tq = lane >> 2;
    const int tc = (lane & 3) * 2;
    #pragma unroll
    for (int nf = 0; nf < 8; nf++) {
        int col = n0 + nf * 8 + tc;
        float2 bv = *(const float2*)&b[col];
        #pragma unroll
        for (int mf = 0; mf < 2; mf++) {
            int r0 = mb + m0 + mf * 16 + tq;
            int r1 = r0 + 8;
            if (r0 < M) {
                float2 o = make_float2(acc[mf][nf][0] + bv.x, acc[mf][nf][1] + bv.y);
                *(float2*)&out[(size_t)r0 * 128 + col] = o;
            }
            if (r1 < M) {
                float2 o = make_float2(acc[mf][nf][2] + bv.x, acc[mf][nf][3] + bv.y);
                *(float2*)&out[(size_t)r1 * 128 + col] = o;
            }
        }
    }
}

// ---------------------------------------------------------------------------
extern "C" void kernel_launch(void* const* d_in, const int* in_sizes, int n_in,
                              void* d_out, int out_size) {
    const float* x  = (const float*)d_in[0];
    const int*   ei = (const int*)d_in[1];
    const float* ew = (const float*)d_in[2];
    const float* W  = (const float*)d_in[3];
    const float* b  = (const float*)d_in[4];
    float*       out = (float*)d_out;

    int N = in_sizes[0] / D;      // 100000
    int E = in_sizes[2];          // 1600000
    int e4 = (E + 3) / 4;

    void* p_cnt = nullptr;
    cudaGetSymbolAddress(&p_cnt, g_cnt);
    cudaMemsetAsync(p_cnt, 0, (size_t)N * sizeof(int));

    fill_kernel<<<(e4 + 255) / 256, 256>>>(ei, ew, E, N);
    int nwarps = (N + 3) / 4;
    aggregate_kernel<<<(nwarps * 32 + 255) / 256, 256>>>(x, N);
    cudaFuncSetAttribute(gemm_hmma_kernel,
                         cudaFuncAttributeMaxDynamicSharedMemorySize, GEMM_SMEM);
    gemm_hmma_kernel<<<(N + 127) / 128, 256, GEMM_SMEM>>>(W, b, out, N);
}

// round 15
// speedup vs baseline: 1.1324x; 1.1324x over previous
#include <cuda_runtime.h>
#include <cuda_fp16.h>
#include <stdint.h>

#define MAX_NODES 100000
#define MAX_EDGES 1600000
#define D 128

typedef unsigned long long ull;

// ---- device scratch ----
__device__ __align__(256) int   g_deg[MAX_NODES];
__device__ __align__(256) int   g_off[MAX_NODES + 1];
__device__ __align__(256) int   g_cur[MAX_NODES];
__device__ __align__(256) unsigned int g_ready[128];
__device__ __align__(256) ull   g_pairs[MAX_EDGES];    // (wt<<32 | src*512)
__device__ __align__(256) float g_agg[(size_t)MAX_NODES * D];

// ---------------------------------------------------------------------------
__global__ void count_kernel(const int* __restrict__ ei, int E, int N) {
    int e4 = blockIdx.x * blockDim.x + threadIdx.x;
    int base = e4 * 4;
    if (base + 4 <= E) {
        int4 d = *(const int4*)(ei + E + base);
        if ((unsigned)d.x < (unsigned)N) atomicAdd(&g_deg[d.x], 1);
        if ((unsigned)d.y < (unsigned)N) atomicAdd(&g_deg[d.y], 1);
        if ((unsigned)d.z < (unsigned)N) atomicAdd(&g_deg[d.z], 1);
        if ((unsigned)d.w < (unsigned)N) atomicAdd(&g_deg[d.w], 1);
    } else {
        for (int e = base; e < E; e++) {
            int dst = ei[E + e];
            if ((unsigned)dst < (unsigned)N) atomicAdd(&g_deg[dst], 1);
        }
    }
}

// Single-kernel scan: per-block scan + publish + parallel lookback.
__global__ __launch_bounds__(1024) void scan_kernel(int n, int nb) {
    __shared__ int warp_sums[32];
    __shared__ int s_carry;
    const int tid  = threadIdx.x;
    const int lane = tid & 31;
    const int wid  = tid >> 5;
    const int bid  = blockIdx.x;
    const int i    = bid * 1024 + tid;

    int v = (i < n) ? g_deg[i] : 0;
    int incl = v;
    #pragma unroll
    for (int d = 1; d < 32; d <<= 1) {
        int t = __shfl_up_sync(0xFFFFFFFFu, incl, d);
        if (lane >= d) incl += t;
    }
    if (lane == 31) warp_sums[wid] = incl;
    __syncthreads();
    if (wid == 0) {
        int wv = warp_sums[lane];
        #pragma unroll
        for (int d = 1; d < 32; d <<= 1) {
            int t = __shfl_up_sync(0xFFFFFFFFu, wv, d);
            if (lane >= d) wv += t;
        }
        warp_sums[lane] = wv;
    }
    __syncthreads();
    const int block_total = warp_sums[31];

    if (tid == 0)
        atomicExch(&g_ready[bid], 0x80000000u | (unsigned)block_total);

    if (wid == 0) {
        unsigned carry = 0;
        bool done = (bid == 0);
        while (!done) {
            unsigned sum = 0;
            bool ok = true;
            for (int j = lane; j < bid; j += 32) {
                unsigned r = *((volatile unsigned*)&g_ready[j]);
                if (!(r & 0x80000000u)) ok = false;
                else sum += r & 0x7FFFFFFFu;
            }
            if (__all_sync(0xFFFFFFFFu, ok)) {
                #pragma unroll
                for (int d = 16; d > 0; d >>= 1)
                    sum += __shfl_down_sync(0xFFFFFFFFu, sum, d);
                carry = sum;
                done = true;
            }
        }
        if (lane == 0) s_carry = (int)carry;
    }
    __syncthreads();

    int base = s_carry + ((wid > 0) ? warp_sums[wid - 1] : 0);
    if (i < n) {
        int ex = base + incl - v;
        g_off[i] = ex;
        g_cur[i] = ex;
    }
    if (bid == nb - 1 && tid == 0) g_off[n] = s_carry + block_total;
}

// CSR fill with MLP=4: 4 edges/thread, independent atomic->scatter chains.
__global__ void fill_kernel(const int* __restrict__ ei,
                            const float* __restrict__ ew, int E, int N) {
    int t = blockIdx.x * blockDim.x + threadIdx.x;
    int base = t * 4;
    if (base + 4 <= E) {
        int4 s = *(const int4*)(ei + base);
        int4 d = *(const int4*)(ei + E + base);
        float4 w = *(const float4*)(ew + base);
        if ((unsigned)d.x < (unsigned)N && (unsigned)s.x < (unsigned)N) {
            int pos = atomicAdd(&g_cur[d.x], 1);
            g_pairs[pos] = ((ull)__float_as_uint(w.x) << 32) | ((unsigned)s.x << 9);
        }
        if ((unsigned)d.y < (unsigned)N && (unsigned)s.y < (unsigned)N) {
            int pos = atomicAdd(&g_cur[d.y], 1);
            g_pairs[pos] = ((ull)__float_as_uint(w.y) << 32) | ((unsigned)s.y << 9);
        }
        if ((unsigned)d.z < (unsigned)N && (unsigned)s.z < (unsigned)N) {
            int pos = atomicAdd(&g_cur[d.z], 1);
            g_pairs[pos] = ((ull)__float_as_uint(w.z) << 32) | ((unsigned)s.z << 9);
        }
        if ((unsigned)d.w < (unsigned)N && (unsigned)s.w < (unsigned)N) {
            int pos = atomicAdd(&g_cur[d.w], 1);
            g_pairs[pos] = ((ull)__float_as_uint(w.w) << 32) | ((unsigned)s.w << 9);
        }
    } else {
        for (int e = base; e < E; e++) {
            int src = ei[e];
            int dst = ei[E + e];
            if ((unsigned)dst < (unsigned)N && (unsigned)src < (unsigned)N) {
                int pos = atomicAdd(&g_cur[dst], 1);
                g_pairs[pos] = ((ull)__float_as_uint(ew[e]) << 32)
                             | ((unsigned)src << 9);
            }
        }
    }
}

// One warp per node; 2-deep gather with pre-scaled byte offsets, <=32 regs.
__global__ __launch_bounds__(256, 8)
void aggregate_kernel(const float* __restrict__ x, int n) {
    int gw   = (blockIdx.x * blockDim.x + threadIdx.x) >> 5;
    int lane = threadIdx.x & 31;
    if (gw >= n) return;
    const char* xb = (const char*)x + lane * 16;
    int i   = g_off[gw];
    int end = g_off[gw + 1];
    float4 a0 = make_float4(0.f, 0.f, 0.f, 0.f);
    float4 a1 = make_float4(0.f, 0.f, 0.f, 0.f);
    for (; i + 2 <= end; i += 2) {
        ull p0 = g_pairs[i];
        ull p1 = g_pairs[i + 1];
        float4 v0 = *(const float4*)(xb + (unsigned)p0);
        float4 v1 = *(const float4*)(xb + (unsigned)p1);
        float w0 = __uint_as_float((unsigned)(p0 >> 32));
        float w1 = __uint_as_float((unsigned)(p1 >> 32));
        a0.x += w0 * v0.x; a0.y += w0 * v0.y; a0.z += w0 * v0.z; a0.w += w0 * v0.w;
        a1.x += w1 * v1.x; a1.y += w1 * v1.y; a1.z += w1 * v1.z; a1.w += w1 * v1.w;
    }
    if (i < end) {
        ull p = g_pairs[i];
        float4 v = *(const float4*)(xb + (unsigned)p);
        float w = __uint_as_float((unsigned)(p >> 32));
        a0.x += w * v.x; a0.y += w * v.y; a0.z += w * v.z; a0.w += w * v.w;
    }
    float4 r = make_float4(a0.x + a1.x, a0.y + a1.y, a0.z + a1.z, a0.w + a1.w);
    *(float4*)(g_agg + (size_t)gw * D + lane * 4) = r;
}

// ============================================================================
// HMMA GEMM (identical to round-10): mma.sync m16n8k16 f16->f32.
// ============================================================================

#define SH_STRIDE 136

__device__ __forceinline__ uint32_t smem_u32(const void* p) {
    return (uint32_t)__cvta_generic_to_shared(p);
}

__device__ __forceinline__ void ldsm_x4(uint32_t& r0, uint32_t& r1,
                                        uint32_t& r2, uint32_t& r3, uint32_t a) {
    asm volatile("ldmatrix.sync.aligned.m8n8.x4.shared.b16 {%0,%1,%2,%3}, [%4];"
                 : "=r"(r0), "=r"(r1), "=r"(r2), "=r"(r3) : "r"(a));
}

__device__ __forceinline__ void hmma(float& c0, float& c1, float& c2, float& c3,
                                     uint32_t a0, uint32_t a1, uint32_t a2, uint32_t a3,
                                     uint32_t b0, uint32_t b1) {
    asm volatile("mma.sync.aligned.m16n8k16.row.col.f32.f16.f16.f32 "
                 "{%0,%1,%2,%3}, {%4,%5,%6,%7}, {%8,%9}, {%0,%1,%2,%3};"
                 : "+f"(c0), "+f"(c1), "+f"(c2), "+f"(c3)
                 : "r"(a0), "r"(a1), "r"(a2), "r"(a3), "r"(b0), "r"(b1));
}

#define GEMM_SMEM (2 * 128 * SH_STRIDE * 2)

__global__ __launch_bounds__(256) void gemm_hmma_kernel(const float* __restrict__ W,
                                                        const float* __restrict__ b,
                                                        float* __restrict__ out, int M) {
    extern __shared__ __align__(16) __half sh[];
    __half* sA = sh;
    __half* sW = sh + 128 * SH_STRIDE;
    const int tid  = threadIdx.x;
    const int wid  = tid >> 5;
    const int lane = tid & 31;
    const int mb   = blockIdx.x * 128;

    for (int idx = tid; idx < 128 * 32; idx += 256) {
        int r = idx >> 5, c4 = idx & 31;
        float4 v = ((const float4*)(W + r * 128))[c4];
        *(__half2*)&sW[r * SH_STRIDE + c4 * 4]     = __floats2half2_rn(v.x, v.y);
        *(__half2*)&sW[r * SH_STRIDE + c4 * 4 + 2] = __floats2half2_rn(v.z, v.w);
    }
    for (int idx = tid; idx < 128 * 32; idx += 256) {
        int r = idx >> 5, c4 = idx & 31;
        int row = mb + r;
        float4 v = (row < M) ? ((const float4*)(g_agg + (size_t)row * 128))[c4]
                             : make_float4(0.f, 0.f, 0.f, 0.f);
        *(__half2*)&sA[r * SH_STRIDE + c4 * 4]     = __floats2half2_rn(v.x, v.y);
        *(__half2*)&sA[r * SH_STRIDE + c4 * 4 + 2] = __floats2half2_rn(v.z, v.w);
    }
    __syncthreads();

    const int m0 = (wid & 3) * 32;
    const int n0 = (wid >> 2) * 64;

    float acc[2][8][4];
    #pragma unroll
    for (int i = 0; i < 2; i++)
        #pragma unroll
        for (int j = 0; j < 8; j++)
            #pragma unroll
            for (int q = 0; q < 4; q++) acc[i][j][q] = 0.f;

    const int a_row_off = lane & 15;
    const int a_col_off = (lane >> 4) * 8;
    const int b_row_off = (lane & 7) + ((lane >> 4) & 1) * 8;
    const int b_col_off = ((lane >> 3) & 1) * 8;

    #pragma unroll
    for (int kt = 0; kt < 8; kt++) {
        const int klo = kt * 16;
        uint32_t af[2][4];
        #pragma unroll
        for (int mf = 0; mf < 2; mf++) {
            uint32_t addr = smem_u32(&sA[(m0 + mf * 16 + a_row_off) * SH_STRIDE
                                         + klo + a_col_off]);
            ldsm_x4(af[mf][0], af[mf][1], af[mf][2], af[mf][3], addr);
        }
        uint32_t bf[8][2];
        #pragma unroll
        for (int g = 0; g < 4; g++) {
            uint32_t r0, r1, r2, r3;
            uint32_t addr = smem_u32(&sW[(n0 + g * 16 + b_row_off) * SH_STRIDE
                                         + klo + b_col_off]);
            ldsm_x4(r0, r1, r2, r3, addr);
            bf[g * 2][0] = r0; bf[g * 2][1] = r1;
            bf[g * 2 + 1][0] = r2; bf[g * 2 + 1][1] = r3;
        }
        #pragma unroll
        for (int mf = 0; mf < 2; mf++)
            #pragma unroll
            for (int nf = 0; nf < 8; nf++)
                hmma(acc[mf][nf][0], acc[mf][nf][1], acc[mf][nf][2], acc[mf][nf][3],
                     af[mf][0], af[mf][1], af[mf][2], af[mf][3],
                     bf[nf][0], bf[nf][1]);
    }

    const int tq = lane >> 2;
    const int tc = (lane & 3) * 2;
    #pragma unroll
    for (int nf = 0; nf < 8; nf++) {
        int col = n0 + nf * 8 + tc;
        float2 bv = *(const float2*)&b[col];
        #pragma unroll
        for (int mf = 0; mf < 2; mf++) {
            int r0 = mb + m0 + mf * 16 + tq;
            int r1 = r0 + 8;
            if (r0 < M) {
                float2 o = make_float2(acc[mf][nf][0] + bv.x, acc[mf][nf][1] + bv.y);
                *(float2*)&out[(size_t)r0 * 128 + col] = o;
            }
            if (r1 < M) {
                float2 o = make_float2(acc[mf][nf][2] + bv.x, acc[mf][nf][3] + bv.y);
                *(float2*)&out[(size_t)r1 * 128 + col] = o;
            }
        }
    }
}

// ---------------------------------------------------------------------------
extern "C" void kernel_launch(void* const* d_in, const int* in_sizes, int n_in,
                              void* d_out, int out_size) {
    const float* x  = (const float*)d_in[0];
    const int*   ei = (const int*)d_in[1];
    const float* ew = (const float*)d_in[2];
    const float* W  = (const float*)d_in[3];
    const float* b  = (const float*)d_in[4];
    float*       out = (float*)d_out;

    int N = in_sizes[0] / D;      // 100000
    int E = in_sizes[2];          // 1600000
    int nb = (N + 1023) / 1024;   // 98
    int e4 = (E + 3) / 4;

    void* p_deg = nullptr; void* p_rdy = nullptr;
    cudaGetSymbolAddress(&p_deg, g_deg);
    cudaGetSymbolAddress(&p_rdy, g_ready);
    cudaMemsetAsync(p_deg, 0, (size_t)N * sizeof(int));
    cudaMemsetAsync(p_rdy, 0, 128 * sizeof(unsigned int));

    count_kernel<<<(e4 + 255) / 256, 256>>>(ei, E, N);              // launch 0
    scan_kernel<<<nb, 1024>>>(N, nb);                               // launch 1
    fill_kernel<<<(e4 + 255) / 256, 256>>>(ei, ew, E, N);           // launch 2
    aggregate_kernel<<<((size_t)N * 32 + 255) / 256, 256>>>(x, N);  // launch 3
    cudaFuncSetAttribute(gemm_hmma_kernel,
                         cudaFuncAttributeMaxDynamicSharedMemorySize, GEMM_SMEM);
    gemm_hmma_kernel<<<(N + 127) / 128, 256, GEMM_SMEM>>>(W, b, out, N);
}

// round 16
// speedup vs baseline: 1.2191x; 1.0766x over previous
#include <cuda_runtime.h>
#include <cuda_fp16.h>
#include <stdint.h>

#define MAX_NODES 100000
#define MAX_EDGES 1600000
#define D 128

typedef unsigned long long ull;

// ---- device scratch ----
__device__ __align__(256) int    g_deg[MAX_NODES];
__device__ __align__(256) int    g_off[MAX_NODES + 1];
__device__ __align__(256) int    g_cur[MAX_NODES];
__device__ __align__(256) unsigned int g_ready[128];
__device__ __align__(256) ull    g_pairs[MAX_EDGES];   // (wt<<32 | src*256)
__device__ __align__(256) __half g_x16[(size_t)MAX_NODES * D];
__device__ __align__(256) float  g_agg[(size_t)MAX_NODES * D];

// ---------------------------------------------------------------------------
// Fused: degree histogram (4 edges/thread) + x fp32->fp16 convert.
__global__ void count_convert_kernel(const int* __restrict__ ei,
                                     const float* __restrict__ x,
                                     int E, int N, int t4) {
    int t = blockIdx.x * blockDim.x + threadIdx.x;
    int base = t * 4;
    if (base + 4 <= E) {
        int4 d = *(const int4*)(ei + E + base);
        if ((unsigned)d.x < (unsigned)N) atomicAdd(&g_deg[d.x], 1);
        if ((unsigned)d.y < (unsigned)N) atomicAdd(&g_deg[d.y], 1);
        if ((unsigned)d.z < (unsigned)N) atomicAdd(&g_deg[d.z], 1);
        if ((unsigned)d.w < (unsigned)N) atomicAdd(&g_deg[d.w], 1);
    } else {
        for (int e = base; e < E; e++) {
            int dst = ei[E + e];
            if ((unsigned)dst < (unsigned)N) atomicAdd(&g_deg[dst], 1);
        }
    }
    if (t < t4) {
        float4 v = ((const float4*)x)[t];
        __half2* o = (__half2*)g_x16 + t * 2;
        o[0] = __floats2half2_rn(v.x, v.y);
        o[1] = __floats2half2_rn(v.z, v.w);
    }
}

// Single-kernel scan: per-block scan + publish + parallel lookback.
__global__ __launch_bounds__(1024) void scan_kernel(int n, int nb) {
    __shared__ int warp_sums[32];
    __shared__ int s_carry;
    const int tid  = threadIdx.x;
    const int lane = tid & 31;
    const int wid  = tid >> 5;
    const int bid  = blockIdx.x;
    const int i    = bid * 1024 + tid;

    int v = (i < n) ? g_deg[i] : 0;
    int incl = v;
    #pragma unroll
    for (int d = 1; d < 32; d <<= 1) {
        int t = __shfl_up_sync(0xFFFFFFFFu, incl, d);
        if (lane >= d) incl += t;
    }
    if (lane == 31) warp_sums[wid] = incl;
    __syncthreads();
    if (wid == 0) {
        int wv = warp_sums[lane];
        #pragma unroll
        for (int d = 1; d < 32; d <<= 1) {
            int t = __shfl_up_sync(0xFFFFFFFFu, wv, d);
            if (lane >= d) wv += t;
        }
        warp_sums[lane] = wv;
    }
    __syncthreads();
    const int block_total = warp_sums[31];

    if (tid == 0)
        atomicExch(&g_ready[bid], 0x80000000u | (unsigned)block_total);

    if (wid == 0) {
        unsigned carry = 0;
        bool done = (bid == 0);
        while (!done) {
            unsigned sum = 0;
            bool ok = true;
            for (int j = lane; j < bid; j += 32) {
                unsigned r = *((volatile unsigned*)&g_ready[j]);
                if (!(r & 0x80000000u)) ok = false;
                else sum += r & 0x7FFFFFFFu;
            }
            if (__all_sync(0xFFFFFFFFu, ok)) {
                #pragma unroll
                for (int d = 16; d > 0; d >>= 1)
                    sum += __shfl_down_sync(0xFFFFFFFFu, sum, d);
                carry = sum;
                done = true;
            }
        }
        if (lane == 0) s_carry = (int)carry;
    }
    __syncthreads();

    int base = s_carry + ((wid > 0) ? warp_sums[wid - 1] : 0);
    if (i < n) {
        int ex = base + incl - v;
        g_off[i] = ex;
        g_cur[i] = ex;
    }
    if (bid == nb - 1 && tid == 0) g_off[n] = s_carry + block_total;
}

// CSR fill, MLP=4; stores pre-scaled fp16-row byte offset (src * 256).
__global__ void fill_kernel(const int* __restrict__ ei,
                            const float* __restrict__ ew, int E, int N) {
    int t = blockIdx.x * blockDim.x + threadIdx.x;
    int base = t * 4;
    if (base + 4 <= E) {
        int4 s = *(const int4*)(ei + base);
        int4 d = *(const int4*)(ei + E + base);
        float4 w = *(const float4*)(ew + base);
        if ((unsigned)d.x < (unsigned)N && (unsigned)s.x < (unsigned)N) {
            int pos = atomicAdd(&g_cur[d.x], 1);
            g_pairs[pos] = ((ull)__float_as_uint(w.x) << 32) | ((unsigned)s.x << 8);
        }
        if ((unsigned)d.y < (unsigned)N && (unsigned)s.y < (unsigned)N) {
            int pos = atomicAdd(&g_cur[d.y], 1);
            g_pairs[pos] = ((ull)__float_as_uint(w.y) << 32) | ((unsigned)s.y << 8);
        }
        if ((unsigned)d.z < (unsigned)N && (unsigned)s.z < (unsigned)N) {
            int pos = atomicAdd(&g_cur[d.z], 1);
            g_pairs[pos] = ((ull)__float_as_uint(w.z) << 32) | ((unsigned)s.z << 8);
        }
        if ((unsigned)d.w < (unsigned)N && (unsigned)s.w < (unsigned)N) {
            int pos = atomicAdd(&g_cur[d.w], 1);
            g_pairs[pos] = ((ull)__float_as_uint(w.w) << 32) | ((unsigned)s.w << 8);
        }
    } else {
        for (int e = base; e < E; e++) {
            int src = ei[e];
            int dst = ei[E + e];
            if ((unsigned)dst < (unsigned)N && (unsigned)src < (unsigned)N) {
                int pos = atomicAdd(&g_cur[dst], 1);
                g_pairs[pos] = ((ull)__float_as_uint(ew[e]) << 32)
                             | ((unsigned)src << 8);
            }
        }
    }
}

// One warp per node; fp16 gather (8 B/lane/edge), fp32 accumulate, <=32 regs.
__global__ __launch_bounds__(256, 8)
void aggregate_kernel(int n) {
    int gw   = (blockIdx.x * blockDim.x + threadIdx.x) >> 5;
    int lane = threadIdx.x & 31;
    if (gw >= n) return;
    const char* xb = (const char*)g_x16 + lane * 8;   // lane's 8B slice base
    int i   = g_off[gw];
    int end = g_off[gw + 1];
    float4 a0 = make_float4(0.f, 0.f, 0.f, 0.f);
    float4 a1 = make_float4(0.f, 0.f, 0.f, 0.f);
    for (; i + 2 <= end; i += 2) {
        ull p0 = g_pairs[i];
        ull p1 = g_pairs[i + 1];
        uint2 u0 = *(const uint2*)(xb + (unsigned)p0);
        uint2 u1 = *(const uint2*)(xb + (unsigned)p1);
        float w0 = __uint_as_float((unsigned)(p0 >> 32));
        float w1 = __uint_as_float((unsigned)(p1 >> 32));
        float2 f0a = __half22float2(*(const __half2*)&u0.x);
        float2 f0b = __half22float2(*(const __half2*)&u0.y);
        float2 f1a = __half22float2(*(const __half2*)&u1.x);
        float2 f1b = __half22float2(*(const __half2*)&u1.y);
        a0.x += w0 * f0a.x; a0.y += w0 * f0a.y; a0.z += w0 * f0b.x; a0.w += w0 * f0b.y;
        a1.x += w1 * f1a.x; a1.y += w1 * f1a.y; a1.z += w1 * f1b.x; a1.w += w1 * f1b.y;
    }
    if (i < end) {
        ull p = g_pairs[i];
        uint2 u = *(const uint2*)(xb + (unsigned)p);
        float w = __uint_as_float((unsigned)(p >> 32));
        float2 fa = __half22float2(*(const __half2*)&u.x);
        float2 fb = __half22float2(*(const __half2*)&u.y);
        a0.x += w * fa.x; a0.y += w * fa.y; a0.z += w * fb.x; a0.w += w * fb.y;
    }
    float4 r = make_float4(a0.x + a1.x, a0.y + a1.y, a0.z + a1.z, a0.w + a1.w);
    *(float4*)(g_agg + (size_t)gw * D + lane * 4) = r;
}

// ============================================================================
// HMMA GEMM (identical to round-10): mma.sync m16n8k16 f16->f32.
// ============================================================================

#define SH_STRIDE 136

__device__ __forceinline__ uint32_t smem_u32(const void* p) {
    return (uint32_t)__cvta_generic_to_shared(p);
}

__device__ __forceinline__ void ldsm_x4(uint32_t& r0, uint32_t& r1,
                                        uint32_t& r2, uint32_t& r3, uint32_t a) {
    asm volatile("ldmatrix.sync.aligned.m8n8.x4.shared.b16 {%0,%1,%2,%3}, [%4];"
                 : "=r"(r0), "=r"(r1), "=r"(r2), "=r"(r3) : "r"(a));
}

__device__ __forceinline__ void hmma(float& c0, float& c1, float& c2, float& c3,
                                     uint32_t a0, uint32_t a1, uint32_t a2, uint32_t a3,
                                     uint32_t b0, uint32_t b1) {
    asm volatile("mma.sync.aligned.m16n8k16.row.col.f32.f16.f16.f32 "
                 "{%0,%1,%2,%3}, {%4,%5,%6,%7}, {%8,%9}, {%0,%1,%2,%3};"
                 : "+f"(c0), "+f"(c1), "+f"(c2), "+f"(c3)
                 : "r"(a0), "r"(a1), "r"(a2), "r"(a3), "r"(b0), "r"(b1));
}

#define GEMM_SMEM (2 * 128 * SH_STRIDE * 2)

__global__ __launch_bounds__(256) void gemm_hmma_kernel(const float* __restrict__ W,
                                                        const float* __restrict__ b,
                                                        float* __restrict__ out, int M) {
    extern __shared__ __align__(16) __half sh[];
    __half* sA = sh;
    __half* sW = sh + 128 * SH_STRIDE;
    const int tid  = threadIdx.x;
    const int wid  = tid >> 5;
    const int lane = tid & 31;
    const int mb   = blockIdx.x * 128;

    for (int idx = tid; idx < 128 * 32; idx += 256) {
        int r = idx >> 5, c4 = idx & 31;
        float4 v = ((const float4*)(W + r * 128))[c4];
        *(__half2*)&sW[r * SH_STRIDE + c4 * 4]     = __floats2half2_rn(v.x, v.y);
        *(__half2*)&sW[r * SH_STRIDE + c4 * 4 + 2] = __floats2half2_rn(v.z, v.w);
    }
    for (int idx = tid; idx < 128 * 32; idx += 256) {
        int r = idx >> 5, c4 = idx & 31;
        int row = mb + r;
        float4 v = (row < M) ? ((const float4*)(g_agg + (size_t)row * 128))[c4]
                             : make_float4(0.f, 0.f, 0.f, 0.f);
        *(__half2*)&sA[r * SH_STRIDE + c4 * 4]     = __floats2half2_rn(v.x, v.y);
        *(__half2*)&sA[r * SH_STRIDE + c4 * 4 + 2] = __floats2half2_rn(v.z, v.w);
    }
    __syncthreads();

    const int m0 = (wid & 3) * 32;
    const int n0 = (wid >> 2) * 64;

    float acc[2][8][4];
    #pragma unroll
    for (int i = 0; i < 2; i++)
        #pragma unroll
        for (int j = 0; j < 8; j++)
            #pragma unroll
            for (int q = 0; q < 4; q++) acc[i][j][q] = 0.f;

    const int a_row_off = lane & 15;
    const int a_col_off = (lane >> 4) * 8;
    const int b_row_off = (lane & 7) + ((lane >> 4) & 1) * 8;
    const int b_col_off = ((lane >> 3) & 1) * 8;

    #pragma unroll
    for (int kt = 0; kt < 8; kt++) {
        const int klo = kt * 16;
        uint32_t af[2][4];
        #pragma unroll
        for (int mf = 0; mf < 2; mf++) {
            uint32_t addr = smem_u32(&sA[(m0 + mf * 16 + a_row_off) * SH_STRIDE
                                         + klo + a_col_off]);
            ldsm_x4(af[mf][0], af[mf][1], af[mf][2], af[mf][3], addr);
        }
        uint32_t bf[8][2];
        #pragma unroll
        for (int g = 0; g < 4; g++) {
            uint32_t r0, r1, r2, r3;
            uint32_t addr = smem_u32(&sW[(n0 + g * 16 + b_row_off) * SH_STRIDE
                                         + klo + b_col_off]);
            ldsm_x4(r0, r1, r2, r3, addr);
            bf[g * 2][0] = r0; bf[g * 2][1] = r1;
            bf[g * 2 + 1][0] = r2; bf[g * 2 + 1][1] = r3;
        }
        #pragma unroll
        for (int mf = 0; mf < 2; mf++)
            #pragma unroll
            for (int nf = 0; nf < 8; nf++)
                hmma(acc[mf][nf][0], acc[mf][nf][1], acc[mf][nf][2], acc[mf][nf][3],
                     af[mf][0], af[mf][1], af[mf][2], af[mf][3],
                     bf[nf][0], bf[nf][1]);
    }

    const int tq = lane >> 2;
    const int tc = (lane & 3) * 2;
    #pragma unroll
    for (int nf = 0; nf < 8; nf++) {
        int col = n0 + nf * 8 + tc;
        float2 bv = *(const float2*)&b[col];
        #pragma unroll
        for (int mf = 0; mf < 2; mf++) {
            int r0 = mb + m0 + mf * 16 + tq;
            int r1 = r0 + 8;
            if (r0 < M) {
                float2 o = make_float2(acc[mf][nf][0] + bv.x, acc[mf][nf][1] + bv.y);
                *(float2*)&out[(size_t)r0 * 128 + col] = o;
            }
            if (r1 < M) {
                float2 o = make_float2(acc[mf][nf][2] + bv.x, acc[mf][nf][3] + bv.y);
                *(float2*)&out[(size_t)r1 * 128 + col] = o;
            }
        }
    }
}

// ---------------------------------------------------------------------------
extern "C" void kernel_launch(void* const* d_in, const int* in_sizes, int n_in,
                              void* d_out, int out_size) {
    const float* x  = (const float*)d_in[0];
    const int*   ei = (const int*)d_in[1];
    const float* ew = (const float*)d_in[2];
    const float* W  = (const float*)d_in[3];
    const float* b  = (const float*)d_in[4];
    float*       out = (float*)d_out;

    int N = in_sizes[0] / D;      // 100000
    int E = in_sizes[2];          // 1600000
    int nb = (N + 1023) / 1024;   // 98
    int e4 = (E + 3) / 4;
    int t4 = (N * D) / 4;         // 3.2M float4s for convert

    void* p_deg = nullptr; void* p_rdy = nullptr;
    cudaGetSymbolAddress(&p_deg, g_deg);
    cudaGetSymbolAddress(&p_rdy, g_ready);
    cudaMemsetAsync(p_deg, 0, (size_t)N * sizeof(int));
    cudaMemsetAsync(p_rdy, 0, 128 * sizeof(unsigned int));

    int cc = (t4 > e4) ? t4 : e4;
    count_convert_kernel<<<(cc + 255) / 256, 256>>>(ei, x, E, N, t4);  // 0
    scan_kernel<<<nb, 1024>>>(N, nb);                                  // 1
    fill_kernel<<<(e4 + 255) / 256, 256>>>(ei, ew, E, N);              // 2
    aggregate_kernel<<<((size_t)N * 32 + 255) / 256, 256>>>(N);        // 3
    cudaFuncSetAttribute(gemm_hmma_kernel,
                         cudaFuncAttributeMaxDynamicSharedMemorySize, GEMM_SMEM);
    gemm_hmma_kernel<<<(N + 127) / 128, 256, GEMM_SMEM>>>(W, b, out, N);
}

// round 17
// speedup vs baseline: 1.3074x; 1.0724x over previous
#include <cuda_runtime.h>
#include <cuda_fp16.h>
#include <stdint.h>

#define MAX_NODES 100000
#define MAX_EDGES 1600000
#define D 128

typedef unsigned long long ull;

// ---- device scratch ----
__device__ __align__(256) int    g_deg[MAX_NODES];
__device__ __align__(256) int    g_off[MAX_NODES + 1];
__device__ __align__(256) int    g_cur[MAX_NODES];
__device__ __align__(256) unsigned int g_ready[128];
__device__ __align__(256) ull    g_pairs[MAX_EDGES];   // (wt<<32 | src*256)
__device__ __align__(256) __half g_x16[(size_t)MAX_NODES * D];
__device__ __align__(256) __half g_agg16[(size_t)MAX_NODES * D];

// ---------------------------------------------------------------------------
// Fused: degree histogram (4 edges/thread) + x fp32->fp16 convert.
__global__ void count_convert_kernel(const int* __restrict__ ei,
                                     const float* __restrict__ x,
                                     int E, int N, int t4) {
    int t = blockIdx.x * blockDim.x + threadIdx.x;
    int base = t * 4;
    if (base + 4 <= E) {
        int4 d = *(const int4*)(ei + E + base);
        if ((unsigned)d.x < (unsigned)N) atomicAdd(&g_deg[d.x], 1);
        if ((unsigned)d.y < (unsigned)N) atomicAdd(&g_deg[d.y], 1);
        if ((unsigned)d.z < (unsigned)N) atomicAdd(&g_deg[d.z], 1);
        if ((unsigned)d.w < (unsigned)N) atomicAdd(&g_deg[d.w], 1);
    } else {
        for (int e = base; e < E; e++) {
            int dst = ei[E + e];
            if ((unsigned)dst < (unsigned)N) atomicAdd(&g_deg[dst], 1);
        }
    }
    if (t < t4) {
        float4 v = ((const float4*)x)[t];
        __half2* o = (__half2*)g_x16 + t * 2;
        o[0] = __floats2half2_rn(v.x, v.y);
        o[1] = __floats2half2_rn(v.z, v.w);
    }
}

// Single-kernel scan: per-block scan + publish + parallel lookback.
__global__ __launch_bounds__(1024) void scan_kernel(int n, int nb) {
    __shared__ int warp_sums[32];
    __shared__ int s_carry;
    const int tid  = threadIdx.x;
    const int lane = tid & 31;
    const int wid  = tid >> 5;
    const int bid  = blockIdx.x;
    const int i    = bid * 1024 + tid;

    int v = (i < n) ? g_deg[i] : 0;
    int incl = v;
    #pragma unroll
    for (int d = 1; d < 32; d <<= 1) {
        int t = __shfl_up_sync(0xFFFFFFFFu, incl, d);
        if (lane >= d) incl += t;
    }
    if (lane == 31) warp_sums[wid] = incl;
    __syncthreads();
    if (wid == 0) {
        int wv = warp_sums[lane];
        #pragma unroll
        for (int d = 1; d < 32; d <<= 1) {
            int t = __shfl_up_sync(0xFFFFFFFFu, wv, d);
            if (lane >= d) wv += t;
        }
        warp_sums[lane] = wv;
    }
    __syncthreads();
    const int block_total = warp_sums[31];

    if (tid == 0)
        atomicExch(&g_ready[bid], 0x80000000u | (unsigned)block_total);

    if (wid == 0) {
        unsigned carry = 0;
        bool done = (bid == 0);
        while (!done) {
            unsigned sum = 0;
            bool ok = true;
            for (int j = lane; j < bid; j += 32) {
                unsigned r = *((volatile unsigned*)&g_ready[j]);
                if (!(r & 0x80000000u)) ok = false;
                else sum += r & 0x7FFFFFFFu;
            }
            if (__all_sync(0xFFFFFFFFu, ok)) {
                #pragma unroll
                for (int d = 16; d > 0; d >>= 1)
                    sum += __shfl_down_sync(0xFFFFFFFFu, sum, d);
                carry = sum;
                done = true;
            }
        }
        if (lane == 0) s_carry = (int)carry;
    }
    __syncthreads();

    int base = s_carry + ((wid > 0) ? warp_sums[wid - 1] : 0);
    if (i < n) {
        int ex = base + incl - v;
        g_off[i] = ex;
        g_cur[i] = ex;
    }
    if (bid == nb - 1 && tid == 0) g_off[n] = s_carry + block_total;
}

// CSR fill, MLP=4; stores pre-scaled fp16-row byte offset (src * 256).
__global__ void fill_kernel(const int* __restrict__ ei,
                            const float* __restrict__ ew, int E, int N) {
    int t = blockIdx.x * blockDim.x + threadIdx.x;
    int base = t * 4;
    if (base + 4 <= E) {
        int4 s = *(const int4*)(ei + base);
        int4 d = *(const int4*)(ei + E + base);
        float4 w = *(const float4*)(ew + base);
        if ((unsigned)d.x < (unsigned)N && (unsigned)s.x < (unsigned)N) {
            int pos = atomicAdd(&g_cur[d.x], 1);
            g_pairs[pos] = ((ull)__float_as_uint(w.x) << 32) | ((unsigned)s.x << 8);
        }
        if ((unsigned)d.y < (unsigned)N && (unsigned)s.y < (unsigned)N) {
            int pos = atomicAdd(&g_cur[d.y], 1);
            g_pairs[pos] = ((ull)__float_as_uint(w.y) << 32) | ((unsigned)s.y << 8);
        }
        if ((unsigned)d.z < (unsigned)N && (unsigned)s.z < (unsigned)N) {
            int pos = atomicAdd(&g_cur[d.z], 1);
            g_pairs[pos] = ((ull)__float_as_uint(w.z) << 32) | ((unsigned)s.z << 8);
        }
        if ((unsigned)d.w < (unsigned)N && (unsigned)s.w < (unsigned)N) {
            int pos = atomicAdd(&g_cur[d.w], 1);
            g_pairs[pos] = ((ull)__float_as_uint(w.w) << 32) | ((unsigned)s.w << 8);
        }
    } else {
        for (int e = base; e < E; e++) {
            int src = ei[e];
            int dst = ei[E + e];
            if ((unsigned)dst < (unsigned)N && (unsigned)src < (unsigned)N) {
                int pos = atomicAdd(&g_cur[dst], 1);
                g_pairs[pos] = ((ull)__float_as_uint(ew[e]) << 32)
                             | ((unsigned)src << 8);
            }
        }
    }
}

// One warp per node; 4-deep fp16 gather into 2 fp32 accumulator sets.
// Output stored directly as fp16 (same rounding the GEMM would apply).
__global__ __launch_bounds__(256, 7)
void aggregate_kernel(int n) {
    int gw   = (blockIdx.x * blockDim.x + threadIdx.x) >> 5;
    int lane = threadIdx.x & 31;
    if (gw >= n) return;
    const char* xb = (const char*)g_x16 + lane * 8;   // lane's 8B slice base
    int i   = g_off[gw];
    int end = g_off[gw + 1];
    float4 a0 = make_float4(0.f, 0.f, 0.f, 0.f);
    float4 a1 = make_float4(0.f, 0.f, 0.f, 0.f);
    for (; i + 4 <= end; i += 4) {
        ull p0 = g_pairs[i];
        ull p1 = g_pairs[i + 1];
        ull p2 = g_pairs[i + 2];
        ull p3 = g_pairs[i + 3];
        uint2 u0 = *(const uint2*)(xb + (unsigned)p0);
        uint2 u1 = *(const uint2*)(xb + (unsigned)p1);
        uint2 u2 = *(const uint2*)(xb + (unsigned)p2);
        uint2 u3 = *(const uint2*)(xb + (unsigned)p3);
        float w0 = __uint_as_float((unsigned)(p0 >> 32));
        float w1 = __uint_as_float((unsigned)(p1 >> 32));
        float w2 = __uint_as_float((unsigned)(p2 >> 32));
        float w3 = __uint_as_float((unsigned)(p3 >> 32));
        float2 f0a = __half22float2(*(const __half2*)&u0.x);
        float2 f0b = __half22float2(*(const __half2*)&u0.y);
        float2 f1a = __half22float2(*(const __half2*)&u1.x);
        float2 f1b = __half22float2(*(const __half2*)&u1.y);
        float2 f2a = __half22float2(*(const __half2*)&u2.x);
        float2 f2b = __half22float2(*(const __half2*)&u2.y);
        float2 f3a = __half22float2(*(const __half2*)&u3.x);
        float2 f3b = __half22float2(*(const __half2*)&u3.y);
        a0.x += w0 * f0a.x; a0.y += w0 * f0a.y; a0.z += w0 * f0b.x; a0.w += w0 * f0b.y;
        a1.x += w1 * f1a.x; a1.y += w1 * f1a.y; a1.z += w1 * f1b.x; a1.w += w1 * f1b.y;
        a0.x += w2 * f2a.x; a0.y += w2 * f2a.y; a0.z += w2 * f2b.x; a0.w += w2 * f2b.y;
        a1.x += w3 * f3a.x; a1.y += w3 * f3a.y; a1.z += w3 * f3b.x; a1.w += w3 * f3b.y;
    }
    for (; i < end; i++) {
        ull p = g_pairs[i];
        uint2 u = *(const uint2*)(xb + (unsigned)p);
        float w = __uint_as_float((unsigned)(p >> 32));
        float2 fa = __half22float2(*(const __half2*)&u.x);
        float2 fb = __half22float2(*(const __half2*)&u.y);
        a0.x += w * fa.x; a0.y += w * fa.y; a0.z += w * fb.x; a0.w += w * fb.y;
    }
    __half2 h0 = __floats2half2_rn(a0.x + a1.x, a0.y + a1.y);
    __half2 h1 = __floats2half2_rn(a0.z + a1.z, a0.w + a1.w);
    uint2 r;
    r.x = *(unsigned*)&h0;
    r.y = *(unsigned*)&h1;
    *(uint2*)((char*)g_agg16 + (size_t)gw * 256 + lane * 8) = r;
}

// ============================================================================
// HMMA GEMM: A staged straight from fp16 g_agg16 (plain copies, no cvt).
// ============================================================================

#define SH_STRIDE 136

__device__ __forceinline__ uint32_t smem_u32(const void* p) {
    return (uint32_t)__cvta_generic_to_shared(p);
}

__device__ __forceinline__ void ldsm_x4(uint32_t& r0, uint32_t& r1,
                                        uint32_t& r2, uint32_t& r3, uint32_t a) {
    asm volatile("ldmatrix.sync.aligned.m8n8.x4.shared.b16 {%0,%1,%2,%3}, [%4];"
                 : "=r"(r0), "=r"(r1), "=r"(r2), "=r"(r3) : "r"(a));
}

__device__ __forceinline__ void hmma(float& c0, float& c1, float& c2, float& c3,
                                     uint32_t a0, uint32_t a1, uint32_t a2, uint32_t a3,
                                     uint32_t b0, uint32_t b1) {
    asm volatile("mma.sync.aligned.m16n8k16.row.col.f32.f16.f16.f32 "
                 "{%0,%1,%2,%3}, {%4,%5,%6,%7}, {%8,%9}, {%0,%1,%2,%3};"
                 : "+f"(c0), "+f"(c1), "+f"(c2), "+f"(c3)
                 : "r"(a0), "r"(a1), "r"(a2), "r"(a3), "r"(b0), "r"(b1));
}

#define GEMM_SMEM (2 * 128 * SH_STRIDE * 2)

__global__ __launch_bounds__(256) void gemm_hmma_kernel(const float* __restrict__ W,
                                                        const float* __restrict__ b,
                                                        float* __restrict__ out, int M) {
    extern __shared__ __align__(16) __half sh[];
    __half* sA = sh;
    __half* sW = sh + 128 * SH_STRIDE;
    const int tid  = threadIdx.x;
    const int wid  = tid >> 5;
    const int lane = tid & 31;
    const int mb   = blockIdx.x * 128;

    for (int idx = tid; idx < 128 * 32; idx += 256) {
        int r = idx >> 5, c4 = idx & 31;
        float4 v = ((const float4*)(W + r * 128))[c4];
        *(__half2*)&sW[r * SH_STRIDE + c4 * 4]     = __floats2half2_rn(v.x, v.y);
        *(__half2*)&sW[r * SH_STRIDE + c4 * 4 + 2] = __floats2half2_rn(v.z, v.w);
    }
    // A tile: plain uint2 copies from fp16 agg (32 uint2 per 256B row).
    for (int idx = tid; idx < 128 * 32; idx += 256) {
        int r = idx >> 5, c8 = idx & 31;
        int row = mb + r;
        uint2 v = (row < M)
            ? *(const uint2*)((const char*)g_agg16 + (size_t)row * 256 + c8 * 8)
            : make_uint2(0u, 0u);
        *(uint2*)&sA[r * SH_STRIDE + c8 * 4] = v;
    }
    __syncthreads();

    const int m0 = (wid & 3) * 32;
    const int n0 = (wid >> 2) * 64;

    float acc[2][8][4];
    #pragma unroll
    for (int i = 0; i < 2; i++)
        #pragma unroll
        for (int j = 0; j < 8; j++)
            #pragma unroll
            for (int q = 0; q < 4; q++) acc[i][j][q] = 0.f;

    const int a_row_off = lane & 15;
    const int a_col_off = (lane >> 4) * 8;
    const int b_row_off = (lane & 7) + ((lane >> 4) & 1) * 8;
    const int b_col_off = ((lane >> 3) & 1) * 8;

    #pragma unroll
    for (int kt = 0; kt < 8; kt++) {
        const int klo = kt * 16;
        uint32_t af[2][4];
        #pragma unroll
        for (int mf = 0; mf < 2; mf++) {
            uint32_t addr = smem_u32(&sA[(m0 + mf * 16 + a_row_off) * SH_STRIDE
                                         + klo + a_col_off]);
            ldsm_x4(af[mf][0], af[mf][1], af[mf][2], af[mf][3], addr);
        }
        uint32_t bf[8][2];
        #pragma unroll
        for (int g = 0; g < 4; g++) {
            uint32_t r0, r1, r2, r3;
            uint32_t addr = smem_u32(&sW[(n0 + g * 16 + b_row_off) * SH_STRIDE
                                         + klo + b_col_off]);
            ldsm_x4(r0, r1, r2, r3, addr);
            bf[g * 2][0] = r0; bf[g * 2][1] = r1;
            bf[g * 2 + 1][0] = r2; bf[g * 2 + 1][1] = r3;
        }
        #pragma unroll
        for (int mf = 0; mf < 2; mf++)
            #pragma unroll
            for (int nf = 0; nf < 8; nf++)
                hmma(acc[mf][nf][0], acc[mf][nf][1], acc[mf][nf][2], acc[mf][nf][3],
                     af[mf][0], af[mf][1], af[mf][2], af[mf][3],
                     bf[nf][0], bf[nf][1]);
    }

    const int tq = lane >> 2;
    const int tc = (lane & 3) * 2;
    #pragma unroll
    for (int nf = 0; nf < 8; nf++) {
        int col = n0 + nf * 8 + tc;
        float2 bv = *(const float2*)&b[col];
        #pragma unroll
        for (int mf = 0; mf < 2; mf++) {
            int r0 = mb + m0 + mf * 16 + tq;
            int r1 = r0 + 8;
            if (r0 < M) {
                float2 o = make_float2(acc[mf][nf][0] + bv.x, acc[mf][nf][1] + bv.y);
                *(float2*)&out[(size_t)r0 * 128 + col] = o;
            }
            if (r1 < M) {
                float2 o = make_float2(acc[mf][nf][2] + bv.x, acc[mf][nf][3] + bv.y);
                *(float2*)&out[(size_t)r1 * 128 + col] = o;
            }
        }
    }
}

// ---------------------------------------------------------------------------
extern "C" void kernel_launch(void* const* d_in, const int* in_sizes, int n_in,
                              void* d_out, int out_size) {
    const float* x  = (const float*)d_in[0];
    const int*   ei = (const int*)d_in[1];
    const float* ew = (const float*)d_in[2];
    const float* W  = (const float*)d_in[3];
    const float* b  = (const float*)d_in[4];
    float*       out = (float*)d_out;

    int N = in_sizes[0] / D;      // 100000
    int E = in_sizes[2];          // 1600000
    int nb = (N + 1023) / 1024;   // 98
    int e4 = (E + 3) / 4;
    int t4 = (N * D) / 4;

    void* p_deg = nullptr; void* p_rdy = nullptr;
    cudaGetSymbolAddress(&p_deg, g_deg);
    cudaGetSymbolAddress(&p_rdy, g_ready);
    cudaMemsetAsync(p_deg, 0, (size_t)N * sizeof(int));
    cudaMemsetAsync(p_rdy, 0, 128 * sizeof(unsigned int));

    int cc = (t4 > e4) ? t4 : e4;
    count_convert_kernel<<<(cc + 255) / 256, 256>>>(ei, x, E, N, t4);  // 0
    scan_kernel<<<nb, 1024>>>(N, nb);                                  // 1
    fill_kernel<<<(e4 + 255) / 256, 256>>>(ei, ew, E, N);              // 2
    aggregate_kernel<<<((size_t)N * 32 + 255) / 256, 256>>>(N);        // 3
    cudaFuncSetAttribute(gemm_hmma_kernel,
                         cudaFuncAttributeMaxDynamicSharedMemorySize, GEMM_SMEM);
    gemm_hmma_kernel<<<(N + 127) / 128, 256, GEMM_SMEM>>>(W, b, out, N);
}